// round 3
// baseline (speedup 1.0000x reference)
#include <cuda_runtime.h>
#include <cuda_bf16.h>

// social_stgcn_46462956208716
//
// The reference ends with log_softmax over a length-1 axis:
//     out = gcn_conv(h, edge_index, W2, b2)   # [16384, 1]
//     return jax.nn.log_softmax(out, axis=1)  # x - logsumexp([x]) == 0
// For any finite input this is identically zero, and all inputs are finite.
// Output = zeros([16384, 1]) exactly; IEEE-754 0.0f is all-zero bytes, so a
// memset fully reproduces it.
//
// We are at the graph-replay floor: the previous 1-kernel version measured
// 4.6 us with 0.0% DRAM (64 KB of stores ~ 8 ns of traffic). Replace the
// kernel node with a graph memset node (cudaMemsetAsync is capturable and
// allocation-free) to skip the kernel-launch path on replay.

extern "C" void kernel_launch(void* const* d_in, const int* in_sizes, int n_in,
                              void* d_out, int out_size) {
    (void)d_in; (void)in_sizes; (void)n_in;
    // float 0.0f == 0x00000000 — byte-wise memset is exact.
    cudaMemsetAsync(d_out, 0, (size_t)out_size * sizeof(float), 0);
}